// round 11
// baseline (speedup 1.0000x reference)
#include <cuda_runtime.h>
#include <cstdint>

#define T_STEPS 2048
#define BATCH 16
#define DIM 1024
#define NCTA 128
#define STEP_ELEMS (BATCH * DIM)                  // 16384
#define OUTS_ELEMS ((size_t)T_STEPS * STEP_ELEMS) // 33554432

// Two independent half-recurrence counters (batches 0-7 / 8-15).
__device__ unsigned int g_cnt[2];

__device__ __forceinline__ float my_tanh(float x) {
    float ax = fabsf(x);
    float e  = __expf(2.0f * ax);
    float r  = 1.0f - 2.0f / (e + 1.0f);
    return copysignf(r, x);
}
__device__ __forceinline__ float my_sigmoid(float x) {
    return 1.0f / (1.0f + __expf(-x));
}

__device__ __forceinline__ void cp_async16(uint32_t smem_addr, const void* gptr) {
    asm volatile("cp.async.cg.shared.global [%0], [%1], 16;\n"
                 :: "r"(smem_addr), "l"(gptr) : "memory");
}
__device__ __forceinline__ void cp_commit() {
    asm volatile("cp.async.commit_group;\n" ::: "memory");
}
#define CP_WAIT(n) asm volatile("cp.async.wait_group %0;\n" :: "n"(n) : "memory")

// Named barrier: 128 threads of one warp-group.
#define GBAR(id) asm volatile("bar.sync %0, 128;" :: "r"(id) : "memory")

__device__ __forceinline__ void arrive_release(unsigned* p) {
    asm volatile("red.add.release.gpu.u32 [%0], %1;" :: "l"(p), "r"(1u) : "memory");
}
__device__ __forceinline__ unsigned ld_acquire(unsigned* p) {
    unsigned v;
    asm volatile("ld.acquire.gpu.u32 %0, [%1];" : "=r"(v) : "l"(p) : "memory");
    return v;
}
__device__ __forceinline__ void st_relaxed_gpu(float* p, float v) {
    asm volatile("st.relaxed.gpu.global.f32 [%0], %1;" :: "l"(p), "f"(v) : "memory");
}

// SW128 swizzle on byte offsets: folds bits [7:10) into [4:7).
__device__ __forceinline__ int swz128(int o) { return o ^ ((o >> 3) & 0x70); }

// ---------------------------------------------------------------------------
// Init: h0 -> hbuf slot 0; reset both counters.
// ---------------------------------------------------------------------------
__global__ void init_kernel(const float* __restrict__ h0, float* __restrict__ hbuf) {
    int i = blockIdx.x * blockDim.x + threadIdx.x;
    if (i < STEP_ELEMS) hbuf[i] = h0[i];
    if (i < 2) g_cnt[i] = 0u;
}

// ---------------------------------------------------------------------------
// Fused persistent kernel. 128 CTAs x 256 threads; CTA owns 8 e-columns.
// Warp-group wg runs an independent half-recurrence (batches [8wg, 8wg+8)).
// Per chain-step:
//   poll (1 thread) -> issue h[t] (2 groups of 4 rows) + x[t+2]
//   -> X-GEMM for wx[t+1] (DOT + reduce) WHILE h is in flight
//   -> 2x (wait h group; H-DOT) -> H-reduce -> finalize -> arrive.
// accX dies before accH is born: R9-level register pressure.
// ---------------------------------------------------------------------------
__global__ void __launch_bounds__(256, 1)
fused_kernel(const float* __restrict__ x,  const float* __restrict__ Wx,
             const float* __restrict__ Wh, const float* __restrict__ bias,
             const float* __restrict__ la, float* __restrict__ outs,
             float* __restrict__ hbuf) {
    extern __shared__ float sm[];
    const int tid   = threadIdx.x;
    const int wg    = tid >> 7;            // chain id
    const int wtid  = tid & 127;
    const int barid = 1 + wg;

    float* h_sh   = sm + wg * 8192;                    // 32 KB / chain
    float* x_shb  = sm + 16384 + wg * 16384;           // 2 bufs x 32 KB / chain
    float* part   = sm + 49152 + wg * 1024;            // 512 float2 / chain
    float* red_sh = sm + 51200 + wg * 64;              // 64 / chain
    float* wxr    = sm + 51328 + wg * 128;             // 2 slots x 64 / chain

    const int ep  = wtid & 3;
    const int c   = wtid >> 2;             // 0..31 k-chunks of 32
    const int e0g = blockIdx.x * 8 + ep * 2;
    const int b0g = wg * 8;

    const float alpha = __expf(la[0]);

    float4 whv[2][8], wxv[2][8];
#pragma unroll
    for (int e = 0; e < 2; e++)
#pragma unroll
        for (int q = 0; q < 8; q++) {
            whv[e][q] = *(const float4*)(Wh + (size_t)(e0g + e) * DIM + c * 32 + q * 4);
            wxv[e][q] = *(const float4*)(Wx + (size_t)(e0g + e) * DIM + c * 32 + q * 4);
        }

    int swz[8];
#pragma unroll
    for (int q = 0; q < 8; q++) swz[q] = swz128(c * 128 + q * 16);

    const uint32_t h_u32 = (uint32_t)__cvta_generic_to_shared(h_sh);
    const uint32_t x_u32 = (uint32_t)__cvta_generic_to_shared(x_shb);

    const int out_id  = wtid & 63;
    const int halfsel = wtid >> 6;
    const int fb  = out_id >> 3;
    const int fe  = out_id & 7;
    const int eg  = blockIdx.x * 8 + fe;
    const int epr = fe >> 1;
    const int el  = fe & 1;
    const float bias_eg = bias[eg];
    const char* hold_p = (const char*)h_sh + fb * 4096 + swz128(eg * 4);

// Issue 32KB x tile (8 batches of step xt) into buffer bufp. One commit group.
#define ISSUE_X(xt, bufp)                                                      \
    do {                                                                       \
        const float4* xs = (const float4*)(x + (size_t)(xt) * STEP_ELEMS       \
                                             + (size_t)b0g * DIM);             \
        uint32_t xb_ = x_u32 + (uint32_t)(bufp) * 32768u;                      \
        _Pragma("unroll")                                                      \
        for (int i = 0; i < 16; i++) {                                         \
            int u = i * 128 + wtid;                                            \
            cp_async16(xb_ + (uint32_t)swz128(u * 16), xs + u);                \
        }                                                                      \
        cp_commit();                                                           \
    } while (0)

// FMA over local batches [B0, B0+NB) from tile SB into ACC[8][2].
#define DOT_RANGE(SB, W, ACC, B0, NB)                                          \
    do {                                                                       \
        _Pragma("unroll")                                                      \
        for (int bb = 0; bb < (NB); bb++) {                                    \
            const int b = (B0) + bb;                                           \
            const char* pb = (const char*)(SB) + b * 4096;                     \
            _Pragma("unroll")                                                  \
            for (int q = 0; q < 8; q++) {                                      \
                float4 v = *(const float4*)(pb + swz[q]);                      \
                _Pragma("unroll")                                              \
                for (int e = 0; e < 2; e++) {                                  \
                    float a = ACC[b][e];                                       \
                    a = fmaf(v.x, W[e][q].x, a);                               \
                    a = fmaf(v.y, W[e][q].y, a);                               \
                    a = fmaf(v.z, W[e][q].z, a);                               \
                    a = fmaf(v.w, W[e][q].w, a);                               \
                    ACC[b][e] = a;                                             \
                }                                                              \
            }                                                                  \
        }                                                                      \
    } while (0)

// Reduce ACC[8][2] over 32 k-chunks -> rsum (pairs with red_sh[out_id]).
#define REDUCE(ACC, rsum)                                                      \
    do {                                                                       \
        _Pragma("unroll")                                                      \
        for (int b = 0; b < 8; b++) {                                          \
            ACC[b][0] += __shfl_xor_sync(0xffffffffu, ACC[b][0], 4);           \
            ACC[b][1] += __shfl_xor_sync(0xffffffffu, ACC[b][1], 4);           \
        }                                                                      \
        if ((wtid & 4) == 0) {                                                 \
            const int p = wtid >> 3;                                           \
            _Pragma("unroll")                                                  \
            for (int b = 0; b < 8; b++) {                                      \
                int idx2 = (p * 8 + b) * 4 + ((ep + p) & 3);                   \
                ((float2*)part)[idx2] = make_float2(ACC[b][0], ACC[b][1]);     \
            }                                                                  \
        }                                                                      \
        GBAR(barid);                                                           \
        {                                                                      \
            float s0 = 0.f, s1 = 0.f;                                          \
            const int pb_ = halfsel * 8;                                       \
            _Pragma("unroll")                                                  \
            for (int u = 0; u < 8; u += 2) {                                   \
                int p0 = pb_ + u, p1 = p0 + 1;                                 \
                s0 += part[((p0 * 8 + fb) * 4 + ((epr + p0) & 3)) * 2 + el];   \
                s1 += part[((p1 * 8 + fb) * 4 + ((epr + p1) & 3)) * 2 + el];   \
            }                                                                  \
            rsum = s0 + s1;                                                    \
        }                                                                      \
        if (halfsel) red_sh[out_id] = rsum;                                    \
        GBAR(barid);                                                           \
    } while (0)

    // ---- Prologue: x[0]->buf0, x[1]->buf1; wx[0] -> wxr slot 0.
    ISSUE_X(0, 0);
    ISSUE_X(1, 1);
    CP_WAIT(1);                // x[0] resident; x[1] pending
    GBAR(barid);
    {
        float accX[8][2];
#pragma unroll
        for (int b = 0; b < 8; b++) { accX[b][0] = accX[b][1] = 0.f; }
        DOT_RANGE(x_shb, wxv, accX, 0, 8);
        float s;
        REDUCE(accX, s);
        if (halfsel == 0) wxr[out_id] = s + red_sh[out_id] + bias_eg;
        GBAR(barid);
    }
    // Loop invariant at top: pending = {x[t+1]}.

    // ---- Main loop (independent per chain).
#pragma unroll 1
    for (int t = 0; t < T_STEPS; t++) {
        const size_t obase = (size_t)t * STEP_ELEMS;

        // Single-thread acquire-poll, barrier release (t=0: init published).
        if (t > 0) {
            if (wtid == 0) {
                const unsigned tgt = (unsigned)t * NCTA;
                while (ld_acquire(&g_cnt[wg]) < tgt) { }
            }
            GBAR(barid);
        }

        // Issue h[t] (8 rows) as 2 groups of 4 rows (16 KB each).
        {
            const float4* src = (const float4*)(hbuf + obase + (size_t)b0g * DIM);
#pragma unroll
            for (int g = 0; g < 2; g++) {
#pragma unroll
                for (int i = 0; i < 8; i++) {
                    int u = g * 1024 + i * 128 + wtid;
                    cp_async16(h_u32 + (uint32_t)swz128(u * 16), src + u);
                }
                cp_commit();
            }
        }
        // Issue x[t+2] into buffer t&1 (consumed next step).
        {
            int xt = (t + 2 <= T_STEPS - 1) ? (t + 2) : (T_STEPS - 1);
            ISSUE_X(xt, t & 1);
        }
        // Queue (oldest first): x[t+1], hA, hB, x[t+2].

        // ---- X-GEMM for wx[t+1] while h[t] is in flight.
        {
            CP_WAIT(3);        // x[t+1] resident
            GBAR(barid);
            const char* xb = (const char*)x_shb + ((t + 1) & 1) * 32768;
            float accX[8][2];
#pragma unroll
            for (int b = 0; b < 8; b++) { accX[b][0] = accX[b][1] = 0.f; }
            DOT_RANGE(xb, wxv, accX, 0, 8);
            float sX;
            REDUCE(accX, sX);
            if (halfsel == 0)
                wxr[((t + 1) & 1) * 64 + out_id] = sX + red_sh[out_id] + bias_eg;
        }

        // ---- H phase.
        float accH[8][2];
#pragma unroll
        for (int b = 0; b < 8; b++) { accH[b][0] = accH[b][1] = 0.f; }

        CP_WAIT(2); GBAR(barid);           // hA resident
        DOT_RANGE(h_sh, whv, accH, 0, 4);
        CP_WAIT(1); GBAR(barid);           // hB resident
        DOT_RANGE(h_sh, whv, accH, 4, 4);

        float sH;
        REDUCE(accH, sH);

        float hn = 0.0f;
        if (halfsel == 0) {
            float pre  = sH + red_sh[out_id] + wxr[(t & 1) * 64 + out_id];
            float hold = *(const float*)hold_p;
            hn = hold + alpha * my_tanh(pre);
            st_relaxed_gpu(&hbuf[(size_t)(t + 1) * STEP_ELEMS
                                 + (size_t)(b0g + fb) * DIM + eg], hn);
        }
        GBAR(barid);               // h stores complete chain-wide

        if (wtid == 0) arrive_release(&g_cnt[wg]);

        // Off-critical-path output.
        if (halfsel == 0) {
            float ot = hn * hn * my_sigmoid(hn);
            outs[obase + (size_t)(b0g + fb) * DIM + eg] = ot;
        }
    }
#undef ISSUE_X
#undef DOT_RANGE
#undef REDUCE
}

// ---------------------------------------------------------------------------
// kernel_launch
//   inputs: x[T,B,D], h0[B,D], W_x[D,D], W_h[D,D], b[D], log_alpha[1]
//   output: [ outs (T*B*D) | h ((T+1)*B*D) ] float32
// ---------------------------------------------------------------------------
extern "C" void kernel_launch(void* const* d_in, const int* in_sizes, int n_in,
                              void* d_out, int out_size) {
    const float* x    = (const float*)d_in[0];
    const float* h0   = (const float*)d_in[1];
    const float* Wx   = (const float*)d_in[2];
    const float* Wh   = (const float*)d_in[3];
    const float* bias = (const float*)d_in[4];
    const float* la   = (const float*)d_in[5];

    float* outs = (float*)d_out;
    float* hbuf = outs + OUTS_ELEMS;

    // floats: h 16384 + x 32768 + part 2048 + red 128 + wxr 256 = 51584
    const int smem_bytes = 51584 * sizeof(float);
    cudaFuncSetAttribute(fused_kernel, cudaFuncAttributeMaxDynamicSharedMemorySize,
                         smem_bytes);

    init_kernel<<<32, 512>>>(h0, hbuf);
    fused_kernel<<<NCTA, 256, smem_bytes>>>(x, Wx, Wh, bias, la, outs, hbuf);
}

// round 12
// speedup vs baseline: 1.2562x; 1.2562x over previous
#include <cuda_runtime.h>
#include <cstdint>

#define T_STEPS 2048
#define BATCH 16
#define DIM 1024
#define NCTA 128
#define STEP_ELEMS (BATCH * DIM)                  // 16384
#define OUTS_ELEMS ((size_t)T_STEPS * STEP_ELEMS) // 33554432

typedef unsigned long long ull;

// Two independent half-recurrence counters (batches 0-7 / 8-15).
__device__ unsigned int g_cnt[2];

__device__ __forceinline__ float my_tanh(float x) {
    float ax = fabsf(x);
    float e  = __expf(2.0f * ax);
    float r  = 1.0f - 2.0f / (e + 1.0f);
    return copysignf(r, x);
}
__device__ __forceinline__ float my_sigmoid(float x) {
    return 1.0f / (1.0f + __expf(-x));
}

__device__ __forceinline__ void cp_async16(uint32_t smem_addr, const void* gptr) {
    asm volatile("cp.async.cg.shared.global [%0], [%1], 16;\n"
                 :: "r"(smem_addr), "l"(gptr) : "memory");
}
__device__ __forceinline__ void cp_commit() {
    asm volatile("cp.async.commit_group;\n" ::: "memory");
}
#define CP_WAIT(n) asm volatile("cp.async.wait_group %0;\n" :: "n"(n) : "memory")

// Named barrier: 128 threads of one warp-group.
#define GBAR(id) asm volatile("bar.sync %0, 128;" :: "r"(id) : "memory")

__device__ __forceinline__ void arrive_release(unsigned* p) {
    asm volatile("red.add.release.gpu.u32 [%0], %1;" :: "l"(p), "r"(1u) : "memory");
}
__device__ __forceinline__ unsigned ld_acquire(unsigned* p) {
    unsigned v;
    asm volatile("ld.acquire.gpu.u32 %0, [%1];" : "=r"(v) : "l"(p) : "memory");
    return v;
}
__device__ __forceinline__ void st_relaxed_gpu(float* p, float v) {
    asm volatile("st.relaxed.gpu.global.f32 [%0], %1;" :: "l"(p), "f"(v) : "memory");
}

// Packed f32x2 FMA: both lanes do IEEE fma. 2 MACs per instruction.
__device__ __forceinline__ void ffma2(ull& a, ull v, ull w) {
    asm("fma.rn.f32x2 %0, %1, %2, %0;" : "+l"(a) : "l"(v), "l"(w));
}
__device__ __forceinline__ float pairsum(ull a) {
    uint32_t lo, hi;
    asm("mov.b64 {%0, %1}, %2;" : "=r"(lo), "=r"(hi) : "l"(a));
    return __uint_as_float(lo) + __uint_as_float(hi);
}

// SW128 swizzle on byte offsets: folds bits [7:10) into [4:7).
__device__ __forceinline__ int swz128(int o) { return o ^ ((o >> 3) & 0x70); }

// ---------------------------------------------------------------------------
// Init: h0 -> hbuf slot 0; reset both counters.
// ---------------------------------------------------------------------------
__global__ void init_kernel(const float* __restrict__ h0, float* __restrict__ hbuf) {
    int i = blockIdx.x * blockDim.x + threadIdx.x;
    if (i < STEP_ELEMS) hbuf[i] = h0[i];
    if (i < 2) g_cnt[i] = 0u;
}

// ---------------------------------------------------------------------------
// Fused persistent kernel (R9 skeleton + fma.rn.f32x2 dot products).
// 128 CTAs x 256 threads; CTA owns 8 e-columns. Warp-group wg runs an
// independent half-recurrence (batches [8wg, 8wg+8)): own smem, own cp.async
// pipeline, own named barrier, own counter.
// Thread: ep = wtid&3 -> e-cols {2ep,2ep+1}; c = wtid>>2 -> k in [32c,32c+32).
// Dot products use packed f32x2 over adjacent-k pairs: LDS.128 yields two
// even-aligned register pairs; weights preloaded as ull pairs. FFMA inst
// count halves vs scalar.
// ---------------------------------------------------------------------------
__global__ void __launch_bounds__(256, 1)
fused_kernel(const float* __restrict__ x,  const float* __restrict__ Wx,
             const float* __restrict__ Wh, const float* __restrict__ bias,
             const float* __restrict__ la, float* __restrict__ outs,
             float* __restrict__ hbuf) {
    extern __shared__ float sm[];
    const int tid   = threadIdx.x;
    const int wg    = tid >> 7;            // chain id
    const int wtid  = tid & 127;
    const int barid = 1 + wg;

    float* h_sh   = sm + wg * 8192;                    // 32 KB / chain
    float* x_shb  = sm + 16384 + wg * 16384;           // 2 bufs x 32 KB / chain
    float* part   = sm + 49152 + wg * 1024;            // 512 float2 / chain
    float* red_sh = sm + 51200 + wg * 64;
    float* wxr    = sm + 51328 + wg * 128;             // 2 slots x 64

    const int ep  = wtid & 3;
    const int c   = wtid >> 2;             // 0..31 k-chunks of 32
    const int e0g = blockIdx.x * 8 + ep * 2;
    const int b0g = wg * 8;

    const float alpha = __expf(la[0]);

    // Weights as packed k-pairs: w[e][2q], w[e][2q+1] for sub-chunk q.
    ull wh2[2][16], wx2[2][16];
#pragma unroll
    for (int e = 0; e < 2; e++)
#pragma unroll
        for (int q = 0; q < 8; q++) {
            ulonglong2 th = *(const ulonglong2*)(Wh + (size_t)(e0g + e) * DIM + c * 32 + q * 4);
            ulonglong2 tx = *(const ulonglong2*)(Wx + (size_t)(e0g + e) * DIM + c * 32 + q * 4);
            wh2[e][2 * q] = th.x; wh2[e][2 * q + 1] = th.y;
            wx2[e][2 * q] = tx.x; wx2[e][2 * q + 1] = tx.y;
        }

    int swz[8];
#pragma unroll
    for (int q = 0; q < 8; q++) swz[q] = swz128(c * 128 + q * 16);

    const uint32_t h_u32 = (uint32_t)__cvta_generic_to_shared(h_sh);
    const uint32_t x_u32 = (uint32_t)__cvta_generic_to_shared(x_shb);

    const int out_id  = wtid & 63;
    const int halfsel = wtid >> 6;
    const int fb  = out_id >> 3;
    const int fe  = out_id & 7;
    const int eg  = blockIdx.x * 8 + fe;
    const int epr = fe >> 1;
    const int el  = fe & 1;
    const float bias_eg = bias[eg];
    const char* hold_p = (const char*)h_sh + fb * 4096 + swz128(eg * 4);

// Issue 32KB x tile (8 batches of step xt) into buffer bufp. One commit group.
#define ISSUE_X(xt, bufp)                                                      \
    do {                                                                       \
        const float4* xs = (const float4*)(x + (size_t)(xt) * STEP_ELEMS       \
                                             + (size_t)b0g * DIM);             \
        uint32_t xb_ = x_u32 + (uint32_t)(bufp) * 32768u;                      \
        _Pragma("unroll")                                                      \
        for (int i = 0; i < 16; i++) {                                         \
            int u = i * 128 + wtid;                                            \
            cp_async16(xb_ + (uint32_t)swz128(u * 16), xs + u);                \
        }                                                                      \
        cp_commit();                                                           \
    } while (0)

// Packed-FMA dot over local batches [B0, B0+NB) from tile SB into ACC2[8][2].
#define DOT_RANGE2(SB, W2, ACC2, B0, NB)                                       \
    do {                                                                       \
        _Pragma("unroll")                                                      \
        for (int bb = 0; bb < (NB); bb++) {                                    \
            const int b = (B0) + bb;                                           \
            const char* pb = (const char*)(SB) + b * 4096;                     \
            _Pragma("unroll")                                                  \
            for (int q = 0; q < 8; q++) {                                      \
                ulonglong2 v = *(const ulonglong2*)(pb + swz[q]);              \
                ffma2(ACC2[b][0], v.x, W2[0][2 * q]);                          \
                ffma2(ACC2[b][0], v.y, W2[0][2 * q + 1]);                      \
                ffma2(ACC2[b][1], v.x, W2[1][2 * q]);                          \
                ffma2(ACC2[b][1], v.y, W2[1][2 * q + 1]);                      \
            }                                                                  \
        }                                                                      \
    } while (0)

// Unpack ull accumulators to scalar ACC[8][2].
#define UNPACK_ACC(ACC2, ACC)                                                  \
    do {                                                                       \
        _Pragma("unroll")                                                      \
        for (int b = 0; b < 8; b++) {                                          \
            ACC[b][0] = pairsum(ACC2[b][0]);                                   \
            ACC[b][1] = pairsum(ACC2[b][1]);                                   \
        }                                                                      \
    } while (0)

// Reduce ACC[8][2] over 32 k-chunks -> rsum (pairs with red_sh[out_id]).
#define REDUCE(ACC, rsum)                                                      \
    do {                                                                       \
        _Pragma("unroll")                                                      \
        for (int b = 0; b < 8; b++) {                                          \
            ACC[b][0] += __shfl_xor_sync(0xffffffffu, ACC[b][0], 4);           \
            ACC[b][1] += __shfl_xor_sync(0xffffffffu, ACC[b][1], 4);           \
        }                                                                      \
        if ((wtid & 4) == 0) {                                                 \
            const int p = wtid >> 3;                                           \
            _Pragma("unroll")                                                  \
            for (int b = 0; b < 8; b++) {                                      \
                int idx2 = (p * 8 + b) * 4 + ((ep + p) & 3);                   \
                ((float2*)part)[idx2] = make_float2(ACC[b][0], ACC[b][1]);     \
            }                                                                  \
        }                                                                      \
        GBAR(barid);                                                           \
        {                                                                      \
            float s0 = 0.f, s1 = 0.f;                                          \
            const int pb_ = halfsel * 8;                                       \
            _Pragma("unroll")                                                  \
            for (int u = 0; u < 8; u += 2) {                                   \
                int p0 = pb_ + u, p1 = p0 + 1;                                 \
                s0 += part[((p0 * 8 + fb) * 4 + ((epr + p0) & 3)) * 2 + el];   \
                s1 += part[((p1 * 8 + fb) * 4 + ((epr + p1) & 3)) * 2 + el];   \
            }                                                                  \
            rsum = s0 + s1;                                                    \
        }                                                                      \
        if (halfsel) red_sh[out_id] = rsum;                                    \
        GBAR(barid);                                                           \
    } while (0)

    // ---- Prologue: x[0]->buf0, x[1]->buf1; wx[0] -> wxr slot 0.
    ISSUE_X(0, 0);
    ISSUE_X(1, 1);
    CP_WAIT(1);                // x[0] resident; x[1] pending
    GBAR(barid);
    {
        ull accX2[8][2];
#pragma unroll
        for (int b = 0; b < 8; b++) { accX2[b][0] = 0ull; accX2[b][1] = 0ull; }
        DOT_RANGE2(x_shb, wx2, accX2, 0, 8);
        float accX[8][2];
        UNPACK_ACC(accX2, accX);
        float s;
        REDUCE(accX, s);
        if (halfsel == 0) wxr[out_id] = s + red_sh[out_id] + bias_eg;
        GBAR(barid);
    }

    // ---- Main loop (independent per chain). R9 choreography verbatim.
#pragma unroll 1
    for (int t = 0; t < T_STEPS; t++) {
        const size_t obase = (size_t)t * STEP_ELEMS;

        // Acquire-poll: this half's h[t] fully published (t=0 from init).
        if (t > 0) {
            const unsigned tgt = (unsigned)t * NCTA;
            while (ld_acquire(&g_cnt[wg]) < tgt) { }
        }

        // Issue this half's h[t] (8 rows) as 4 groups of 2 rows (8 KB each).
        {
            const float4* src = (const float4*)(hbuf + obase + (size_t)b0g * DIM);
#pragma unroll
            for (int g = 0; g < 4; g++) {
#pragma unroll
                for (int i = 0; i < 4; i++) {
                    int u = g * 512 + i * 128 + wtid;
                    cp_async16(h_u32 + (uint32_t)swz128(u * 16), src + u);
                }
                cp_commit();
            }
        }
        // Prefetch x[t+1] into buffer (t+1)&1 (consumed in this step's tail).
        {
            int xt = (t + 1 <= T_STEPS - 1) ? (t + 1) : (T_STEPS - 1);
            ISSUE_X(xt, (t + 1) & 1);
        }

        ull accH2[8][2];
#pragma unroll
        for (int b = 0; b < 8; b++) { accH2[b][0] = 0ull; accH2[b][1] = 0ull; }

        CP_WAIT(4); GBAR(barid); DOT_RANGE2(h_sh, wh2, accH2, 0, 2);
        CP_WAIT(3); GBAR(barid); DOT_RANGE2(h_sh, wh2, accH2, 2, 2);
        CP_WAIT(2); GBAR(barid); DOT_RANGE2(h_sh, wh2, accH2, 4, 2);
        CP_WAIT(1); GBAR(barid); DOT_RANGE2(h_sh, wh2, accH2, 6, 2);

        float hn = 0.0f;
        {
            float accH[8][2];
            UNPACK_ACC(accH2, accH);
            float s;
            REDUCE(accH, s);
            if (halfsel == 0) {
                float pre  = s + red_sh[out_id] + wxr[(t & 1) * 64 + out_id];
                float hold = *(const float*)hold_p;
                hn = hold + alpha * my_tanh(pre);
                st_relaxed_gpu(&hbuf[(size_t)(t + 1) * STEP_ELEMS
                                     + (size_t)(b0g + fb) * DIM + eg], hn);
            }
        }
        GBAR(barid);               // h stores + hold reads complete group-wide

        if (wtid == 0) arrive_release(&g_cnt[wg]);

        // Off-critical-path: silu output store overlaps peers' polls.
        if (halfsel == 0) {
            float ot = hn * hn * my_sigmoid(hn);
            outs[obase + (size_t)(b0g + fb) * DIM + eg] = ot;
        }

        // GEMM tail: wx[t+1] into ring slot (t+1)&1.
        CP_WAIT(0);
        if (t < T_STEPS - 1) {
            GBAR(barid);
            const char* xb = (const char*)x_shb + ((t + 1) & 1) * 32768;
            ull accX2[8][2];
#pragma unroll
            for (int b = 0; b < 8; b++) { accX2[b][0] = 0ull; accX2[b][1] = 0ull; }
            DOT_RANGE2(xb, wx2, accX2, 0, 8);
            float accX[8][2];
            UNPACK_ACC(accX2, accX);
            float s;
            REDUCE(accX, s);
            if (halfsel == 0)
                wxr[((t + 1) & 1) * 64 + out_id] = s + red_sh[out_id] + bias_eg;
        }
    }
#undef ISSUE_X
#undef DOT_RANGE2
#undef UNPACK_ACC
#undef REDUCE
}

// ---------------------------------------------------------------------------
// kernel_launch
//   inputs: x[T,B,D], h0[B,D], W_x[D,D], W_h[D,D], b[D], log_alpha[1]
//   output: [ outs (T*B*D) | h ((T+1)*B*D) ] float32
// ---------------------------------------------------------------------------
extern "C" void kernel_launch(void* const* d_in, const int* in_sizes, int n_in,
                              void* d_out, int out_size) {
    const float* x    = (const float*)d_in[0];
    const float* h0   = (const float*)d_in[1];
    const float* Wx   = (const float*)d_in[2];
    const float* Wh   = (const float*)d_in[3];
    const float* bias = (const float*)d_in[4];
    const float* la   = (const float*)d_in[5];

    float* outs = (float*)d_out;
    float* hbuf = outs + OUTS_ELEMS;

    // floats: h 16384 + x 32768 + part 2048 + red 128 + wxr 256 = 51584
    const int smem_bytes = 51584 * sizeof(float);
    cudaFuncSetAttribute(fused_kernel, cudaFuncAttributeMaxDynamicSharedMemorySize,
                         smem_bytes);

    init_kernel<<<32, 512>>>(h0, hbuf);
    fused_kernel<<<NCTA, 256, smem_bytes>>>(x, Wx, Wh, bias, la, outs, hbuf);
}